// round 14
// baseline (speedup 1.0000x reference)
#include <cuda_runtime.h>

typedef unsigned long long ull;

#define THREADS 256
#define SMEM_FLOATS 57344             // dup table: 3 quad arrays + 1 pair array
#define SMEM_BYTES  (SMEM_FLOATS * 4) // 229376 B (staging reuses this after mainloop)

__device__ __forceinline__ ull pack2(float lo, float hi) {
    ull r; asm("mov.b64 %0, {%1, %2};" : "=l"(r) : "f"(lo), "f"(hi)); return r;
}
__device__ __forceinline__ void unpack2(ull v, float& lo, float& hi) {
    asm("mov.b64 {%0, %1}, %2;" : "=f"(lo), "=f"(hi) : "l"(v));
}
__device__ __forceinline__ ull mul2(ull a, ull b) {
    ull d; asm("mul.rn.f32x2 %0, %1, %2;" : "=l"(d) : "l"(a), "l"(b)); return d;
}
__device__ __forceinline__ ull fma2(ull a, ull b, ull c) {
    ull d; asm("fma.rn.f32x2 %0, %1, %2, %3;" : "=l"(d) : "l"(a), "l"(b), "l"(c)); return d;
}

// One membership level for 4 elements into LOCAL-memory pair arrays
// (rolled t-loop + pointer stores so ptxas keeps them in local).
__device__ __forceinline__ void memb_level(
    const float* __restrict__ x, const float* __restrict__ centers,
    const float* __restrict__ sigmas, int i,
    int b0, int b1, int b2, int b3,
    ull* LP, ull* LQ,
    float& den0, float& den1, float& den2, float& den3)
{
    float x0 = x[b0 * 6 + i];
    float x1 = x[b1 * 6 + i];
    float x2 = x[b2 * 6 + i];
    float x3 = x[b3 * 6 + i];
    float s0 = 0.0f, s1 = 0.0f, s2 = 0.0f, s3 = 0.0f;
#pragma unroll 1
    for (int t = 0; t < 4; t++) {
        float c   = centers[i * 4 + t];
        float sg  = fabsf(sigmas[i * 4 + t]) + 1e-6f;
        float inv = 0.5f / (sg * sg);
        float e0 = x0 - c, e1 = x1 - c, e2 = x2 - c, e3 = x3 - c;
        float v0 = __expf(-e0 * e0 * inv);
        float v1 = __expf(-e1 * e1 * inv);
        float v2 = __expf(-e2 * e2 * inv);
        float v3 = __expf(-e3 * e3 * inv);
        s0 += v0; s1 += v1; s2 += v2; s3 += v3;
        LP[t] = pack2(v0, v1);
        LQ[t] = pack2(v2, v3);
    }
    den0 *= s0; den1 *= s1; den2 *= s2; den3 *= s3;
}

// ANFIS:
//   den[b] = prod_i (sum_t mu[b,i,t])
//   G[b,j] = sum_r w[b,r] * C[r,j]  (hierarchical base-4 partial products)
//   out[b] = (sum_j xa[b,j] * G[b,j]) / (den[b] + 1e-8)
// f32x2 packs ELEMENT PAIRS (P=(b0,b1), Q=(b2,b3); 4 elements/thread).
// Coefficients PRE-DUPLICATED in smem -> every LDS yields ready f32x2
// operands, ZERO duplication MOVs.
// KEY CHANGE vs R9-R13: 256 threads/block -> 255-register budget. The
// 128-reg ceiling at 512 threads forced spills AND just-in-time LDS
// scheduling (exposed 29-cyc latency per body). With ~120 regs of slack,
// ptxas hoists the 16-rule body's 64 LDS ahead of the FMA stream; the 14
// independent accumulator chains then keep the FFMA2 pipe saturated with
// only 2 warps/SMSP.
// 8 warps/block = 4 rule-quarters (fixed d0) x 2 element-warps.
// Quarter partials combined by REUSING the table smem after the mainloop.
__global__ void __launch_bounds__(THREADS, 1) anfis_kernel(
    const float* __restrict__ x,
    const float* __restrict__ centers,
    const float* __restrict__ sigmas,
    const float* __restrict__ cons,
    float* __restrict__ out)
{
    extern __shared__ float sm[];

    // --- Build duplicated table ---
    for (int idx = threadIdx.x; idx < 4096 * 7; idx += THREADS) {
        int r = idx / 7;
        int j = idx - r * 7;
        float v = cons[idx];
        float* dst;
        if (j < 6) dst = sm + ((j >> 1) << 14) + r * 4 + ((j & 1) << 1);
        else       dst = sm + 49152 + r * 2;
        dst[0] = v;
        dst[1] = v;
    }

    int lane  = threadIdx.x & 31;
    int warp  = threadIdx.x >> 5;
    int rs    = warp >> 1;               // rule quarter 0..3 (fixed d0)
    int eslot = (warp & 1) * 32 + lane;  // 0..63
    int q     = blockIdx.x * 64 + eslot;

    int b0 = q, b1 = q + 8192, b2 = q + 16384, b3 = q + 24576;

    // --- Memberships: levels 0-3 local, levels 4-5 registers ---
    ull l0P[4], l0Q[4], l1P[4], l1Q[4], l2P[4], l2Q[4], l3P[4], l3Q[4];
    ull m4P[4], m4Q[4], m5P[4], m5Q[4];
    float den0 = 1.0f, den1 = 1.0f, den2 = 1.0f, den3 = 1.0f;

    memb_level(x, centers, sigmas, 0, b0, b1, b2, b3, l0P, l0Q, den0, den1, den2, den3);
    memb_level(x, centers, sigmas, 1, b0, b1, b2, b3, l1P, l1Q, den0, den1, den2, den3);
    memb_level(x, centers, sigmas, 2, b0, b1, b2, b3, l2P, l2Q, den0, den1, den2, den3);
    memb_level(x, centers, sigmas, 3, b0, b1, b2, b3, l3P, l3Q, den0, den1, den2, den3);
#pragma unroll
    for (int i = 4; i < 6; i++) {   // levels 4,5 -> registers (static indices)
        float x0 = x[b0 * 6 + i];
        float x1 = x[b1 * 6 + i];
        float x2 = x[b2 * 6 + i];
        float x3 = x[b3 * 6 + i];
        float s0 = 0.0f, s1 = 0.0f, s2 = 0.0f, s3 = 0.0f;
#pragma unroll
        for (int t = 0; t < 4; t++) {
            float c   = centers[i * 4 + t];
            float sg  = fabsf(sigmas[i * 4 + t]) + 1e-6f;
            float inv = 0.5f / (sg * sg);
            float e0 = x0 - c, e1 = x1 - c, e2 = x2 - c, e3 = x3 - c;
            float v0 = __expf(-e0 * e0 * inv);
            float v1 = __expf(-e1 * e1 * inv);
            float v2 = __expf(-e2 * e2 * inv);
            float v3 = __expf(-e3 * e3 * inv);
            s0 += v0; s1 += v1; s2 += v2; s3 += v3;
            if (i == 4) { m4P[t] = pack2(v0, v1); m4Q[t] = pack2(v2, v3); }
            else        { m5P[t] = pack2(v0, v1); m5Q[t] = pack2(v2, v3); }
        }
        den0 *= s0; den1 *= s1; den2 *= s2; den3 *= s3;
    }

    int d0 = rs;
    ull A0P = l0P[d0];
    ull A0Q = l0Q[d0];
    __syncthreads();

    const ulonglong2* Q0 = (const ulonglong2*)(sm);
    const ulonglong2* Q1 = (const ulonglong2*)(sm + 16384);
    const ulonglong2* Q2 = (const ulonglong2*)(sm + 32768);
    const ull*        P6 = (const ull*)(sm + 49152);

    ull accP[7], accQ[7];
#pragma unroll
    for (int j = 0; j < 7; j++) { accP[j] = 0; accQ[j] = 0; }

#pragma unroll 1
    for (int d1 = 0; d1 < 4; d1++) {
        ull A1P = mul2(A0P, l1P[d1]);
        ull A1Q = mul2(A0Q, l1Q[d1]);
#pragma unroll 1
        for (int d2 = 0; d2 < 4; d2++) {
            ull A2P = mul2(A1P, l2P[d2]);
            ull A2Q = mul2(A1Q, l2Q[d2]);
#pragma unroll 1
            for (int d3 = 0; d3 < 4; d3++) {
                ull A3P = mul2(A2P, l3P[d3]);
                ull A3Q = mul2(A2Q, l3Q[d3]);
                int rbase = d0 * 1024 + d1 * 256 + d2 * 64 + d3 * 16;
#pragma unroll
                for (int d4 = 0; d4 < 4; d4++) {
                    ull A4P = mul2(A3P, m4P[d4]);
                    ull A4Q = mul2(A3Q, m4Q[d4]);
                    int r = rbase + d4 * 4;
#pragma unroll
                    for (int d5 = 0; d5 < 4; d5++) {
                        ull wP = mul2(A4P, m5P[d5]);
                        ull wQ = mul2(A4Q, m5Q[d5]);
                        ulonglong2 q0 = Q0[r + d5];
                        ulonglong2 q1 = Q1[r + d5];
                        ulonglong2 q2 = Q2[r + d5];
                        ull        p6 = P6[r + d5];
                        accP[0] = fma2(wP, q0.x, accP[0]);
                        accQ[0] = fma2(wQ, q0.x, accQ[0]);
                        accP[1] = fma2(wP, q0.y, accP[1]);
                        accQ[1] = fma2(wQ, q0.y, accQ[1]);
                        accP[2] = fma2(wP, q1.x, accP[2]);
                        accQ[2] = fma2(wQ, q1.x, accQ[2]);
                        accP[3] = fma2(wP, q1.y, accP[3]);
                        accQ[3] = fma2(wQ, q1.y, accQ[3]);
                        accP[4] = fma2(wP, q2.x, accP[4]);
                        accQ[4] = fma2(wQ, q2.x, accQ[4]);
                        accP[5] = fma2(wP, q2.y, accP[5]);
                        accQ[5] = fma2(wQ, q2.y, accQ[5]);
                        accP[6] = fma2(wP, p6, accP[6]);
                        accQ[6] = fma2(wQ, p6, accQ[6]);
                    }
                }
            }
        }
    }

    // --- Quarter combine: REUSE table smem as staging (all reads done) ---
    __syncthreads();
    if (rs != 0) {
        float* base = sm + ((rs - 1) * 64 + eslot) * 29;
#pragma unroll
        for (int j = 0; j < 7; j++) {
            float a, bf, c2, d2v;
            unpack2(accP[j], a, bf);
            unpack2(accQ[j], c2, d2v);
            base[j * 4 + 0] = a;
            base[j * 4 + 1] = bf;
            base[j * 4 + 2] = c2;
            base[j * 4 + 3] = d2v;
        }
    }
    __syncthreads();

    if (rs == 0) {
        float g0[7], g1[7], g2[7], g3[7];
#pragma unroll
        for (int j = 0; j < 7; j++) {
            unpack2(accP[j], g0[j], g1[j]);
            unpack2(accQ[j], g2[j], g3[j]);
        }
#pragma unroll 1
        for (int o = 0; o < 3; o++) {
            const float* base = sm + (o * 64 + eslot) * 29;
#pragma unroll
            for (int j = 0; j < 7; j++) {
                g0[j] += base[j * 4 + 0];
                g1[j] += base[j * 4 + 1];
                g2[j] += base[j * 4 + 2];
                g3[j] += base[j * 4 + 3];
            }
        }
        float n0 = g0[6], n1 = g1[6], n2 = g2[6], n3 = g3[6];
#pragma unroll
        for (int i = 0; i < 6; i++) {
            n0 += g0[i] * x[b0 * 6 + i];
            n1 += g1[i] * x[b1 * 6 + i];
            n2 += g2[i] * x[b2 * 6 + i];
            n3 += g3[i] * x[b3 * 6 + i];
        }
        out[b0] = n0 / (den0 + 1e-8f);
        out[b1] = n1 / (den1 + 1e-8f);
        out[b2] = n2 / (den2 + 1e-8f);
        out[b3] = n3 / (den3 + 1e-8f);
    }
}

extern "C" void kernel_launch(void* const* d_in, const int* in_sizes, int n_in,
                              void* d_out, int out_size) {
    const float* x       = (const float*)d_in[0];
    const float* centers = (const float*)d_in[1];
    const float* sigmas  = (const float*)d_in[2];
    const float* cons    = (const float*)d_in[3];
    float* out = (float*)d_out;

    int B = in_sizes[0] / 6;        // 32768
    int blocks = B / 256;           // 128 (64 eslots x 4 batch quarters)

    cudaFuncSetAttribute(anfis_kernel,
                         cudaFuncAttributeMaxDynamicSharedMemorySize, SMEM_BYTES);

    anfis_kernel<<<blocks, THREADS, SMEM_BYTES>>>(x, centers, sigmas, cons, out);
}

// round 15
// speedup vs baseline: 1.0305x; 1.0305x over previous
#include <cuda_runtime.h>

typedef unsigned long long ull;

#define THREADS 512
#define TABLE_FLOATS (7 * 4096)               // j-major coefficient table (112 KB)
#define SMEM_BYTES   (TABLE_FLOATS * 4)       // 114688 B (staging reuses table)

__device__ __forceinline__ ull pack2(float lo, float hi) {
    ull r; asm("mov.b64 %0, {%1, %2};" : "=l"(r) : "f"(lo), "f"(hi)); return r;
}
__device__ __forceinline__ void unpack2(ull v, float& lo, float& hi) {
    asm("mov.b64 {%0, %1}, %2;" : "=f"(lo), "=f"(hi) : "l"(v));
}
__device__ __forceinline__ ull mul2(ull a, ull b) {
    ull d; asm("mul.rn.f32x2 %0, %1, %2;" : "=l"(d) : "l"(a), "l"(b)); return d;
}
__device__ __forceinline__ ull fma2(ull a, ull b, ull c) {
    ull d; asm("fma.rn.f32x2 %0, %1, %2, %3;" : "=l"(d) : "l"(a), "l"(b), "l"(c)); return d;
}

// One membership level for 4 elements into LOCAL-memory DUPLICATED-pair
// arrays (rolled t-loop + pointer stores keep them out of registers).
__device__ __forceinline__ void memb_level_dup(
    const float* __restrict__ x, const float* __restrict__ centers,
    const float* __restrict__ sigmas, int i,
    int b0, int b1, int b2, int b3,
    ull* L0, ull* L1, ull* L2, ull* L3,
    float& den0, float& den1, float& den2, float& den3)
{
    float x0 = x[b0 * 6 + i];
    float x1 = x[b1 * 6 + i];
    float x2 = x[b2 * 6 + i];
    float x3 = x[b3 * 6 + i];
    float s0 = 0.0f, s1 = 0.0f, s2 = 0.0f, s3 = 0.0f;
#pragma unroll 1
    for (int t = 0; t < 4; t++) {
        float c   = centers[i * 4 + t];
        float sg  = fabsf(sigmas[i * 4 + t]) + 1e-6f;
        float inv = 0.5f / (sg * sg);
        float e0 = x0 - c, e1 = x1 - c, e2 = x2 - c, e3 = x3 - c;
        float v0 = __expf(-e0 * e0 * inv);
        float v1 = __expf(-e1 * e1 * inv);
        float v2 = __expf(-e2 * e2 * inv);
        float v3 = __expf(-e3 * e3 * inv);
        s0 += v0; s1 += v1; s2 += v2; s3 += v3;
        L0[t] = pack2(v0, v0);
        L1[t] = pack2(v1, v1);
        L2[t] = pack2(v2, v2);
        L3[t] = pack2(v3, v3);
    }
    den0 *= s0; den1 *= s1; den2 *= s2; den3 *= s3;
}

// ANFIS:
//   den[b] = prod_i (sum_t mu[b,i,t])
//   G[b,j] = sum_r w[b,r] * C[r,j]  (hierarchical base-4 partial products)
//   out[b] = (sum_j xa[b,j] * G[b,j]) / (den[b] + 1e-8)
// BEST-MIX configuration:
//   * f32x2 packs RULE PAIRS -> the (c.x,c.y)/(c.z,c.w) halves of each
//     j-major float4 table load are ready operands: ZERO duplication MOVs.
//   * 4 elements per thread -> the 7 LDS/4-rule body are amortized over
//     4 elements: LDS issue (~28 cyc/body at the nw>=4 crossbar floor)
//     stays well under the 68 fma-op body.
//   * per body: 68 fma-pipe + 7 LDS + ~3 addr = 78 slots (87% fma ceiling)
//   * levels 1-3 in LOCAL memory (rolled d1/d2/d3 reads), level 0/4/5 and
//     the 28 accumulators in registers (~110 persistent regs at 128 cap)
// 16 warps/block = 8 rule-octants (d0, half of d1) x 2 element-warps;
// octant partials combined by REUSING the table smem after the mainloop.
__global__ void __launch_bounds__(THREADS, 1) anfis_kernel(
    const float* __restrict__ x,
    const float* __restrict__ centers,
    const float* __restrict__ sigmas,
    const float* __restrict__ cons,
    float* __restrict__ out)
{
    extern __shared__ float sm[];

    // --- Build j-major table: sm[j*4096 + r] = cons[r*7 + j] ---
    for (int idx = threadIdx.x; idx < TABLE_FLOATS; idx += THREADS) {
        int j = idx >> 12;
        int r = idx & 4095;
        sm[idx] = cons[r * 7 + j];
    }

    int lane  = threadIdx.x & 31;
    int warp  = threadIdx.x >> 5;
    int rs    = warp >> 1;               // rule octant 0..7
    int d0    = rs >> 1;
    int d1h   = rs & 1;
    int eslot = (warp & 1) * 32 + lane;  // 0..63
    int q     = blockIdx.x * 64 + eslot;

    int b0 = q, b1 = q + 8192, b2 = q + 16384, b3 = q + 24576;

    // --- Memberships: levels 1-3 local (dup pairs), 0/4/5 registers ---
    ull l1_0[4], l1_1[4], l1_2[4], l1_3[4];
    ull l2_0[4], l2_1[4], l2_2[4], l2_3[4];
    ull l3_0[4], l3_1[4], l3_2[4], l3_3[4];
    ull A0_0, A0_1, A0_2, A0_3;          // dup of mu0[d0]
    ull m4_0[4], m4_1[4], m4_2[4], m4_3[4];
    ull p01_0, p23_0, p01_1, p23_1, p01_2, p23_2, p01_3, p23_3;
    float den0 = 1.0f, den1 = 1.0f, den2 = 1.0f, den3 = 1.0f;

    {   // level 0 -> A0 dup registers (select t == d0)
        float x0 = x[b0 * 6], x1 = x[b1 * 6], x2 = x[b2 * 6], x3 = x[b3 * 6];
        float s0 = 0.0f, s1 = 0.0f, s2 = 0.0f, s3 = 0.0f;
        A0_0 = A0_1 = A0_2 = A0_3 = 0;
#pragma unroll 1
        for (int t = 0; t < 4; t++) {
            float c   = centers[t];
            float sg  = fabsf(sigmas[t]) + 1e-6f;
            float inv = 0.5f / (sg * sg);
            float e0 = x0 - c, e1 = x1 - c, e2 = x2 - c, e3 = x3 - c;
            float v0 = __expf(-e0 * e0 * inv);
            float v1 = __expf(-e1 * e1 * inv);
            float v2 = __expf(-e2 * e2 * inv);
            float v3 = __expf(-e3 * e3 * inv);
            s0 += v0; s1 += v1; s2 += v2; s3 += v3;
            if (t == d0) {
                A0_0 = pack2(v0, v0); A0_1 = pack2(v1, v1);
                A0_2 = pack2(v2, v2); A0_3 = pack2(v3, v3);
            }
        }
        den0 *= s0; den1 *= s1; den2 *= s2; den3 *= s3;
    }
    memb_level_dup(x, centers, sigmas, 1, b0, b1, b2, b3,
                   l1_0, l1_1, l1_2, l1_3, den0, den1, den2, den3);
    memb_level_dup(x, centers, sigmas, 2, b0, b1, b2, b3,
                   l2_0, l2_1, l2_2, l2_3, den0, den1, den2, den3);
    memb_level_dup(x, centers, sigmas, 3, b0, b1, b2, b3,
                   l3_0, l3_1, l3_2, l3_3, den0, den1, den2, den3);
    {   // level 4 -> duplicated register pairs
        float x0 = x[b0 * 6 + 4], x1 = x[b1 * 6 + 4];
        float x2 = x[b2 * 6 + 4], x3 = x[b3 * 6 + 4];
        float s0 = 0.0f, s1 = 0.0f, s2 = 0.0f, s3 = 0.0f;
#pragma unroll
        for (int t = 0; t < 4; t++) {
            float c   = centers[16 + t];
            float sg  = fabsf(sigmas[16 + t]) + 1e-6f;
            float inv = 0.5f / (sg * sg);
            float e0 = x0 - c, e1 = x1 - c, e2 = x2 - c, e3 = x3 - c;
            float v0 = __expf(-e0 * e0 * inv);
            float v1 = __expf(-e1 * e1 * inv);
            float v2 = __expf(-e2 * e2 * inv);
            float v3 = __expf(-e3 * e3 * inv);
            s0 += v0; s1 += v1; s2 += v2; s3 += v3;
            m4_0[t] = pack2(v0, v0); m4_1[t] = pack2(v1, v1);
            m4_2[t] = pack2(v2, v2); m4_3[t] = pack2(v3, v3);
        }
        den0 *= s0; den1 *= s1; den2 *= s2; den3 *= s3;
    }
    {   // level 5 -> natural rule pairs
        float x0 = x[b0 * 6 + 5], x1 = x[b1 * 6 + 5];
        float x2 = x[b2 * 6 + 5], x3 = x[b3 * 6 + 5];
        float v0[4], v1[4], v2[4], v3[4];
        float s0 = 0.0f, s1 = 0.0f, s2 = 0.0f, s3 = 0.0f;
#pragma unroll
        for (int t = 0; t < 4; t++) {
            float c   = centers[20 + t];
            float sg  = fabsf(sigmas[20 + t]) + 1e-6f;
            float inv = 0.5f / (sg * sg);
            float e0 = x0 - c, e1 = x1 - c, e2 = x2 - c, e3 = x3 - c;
            v0[t] = __expf(-e0 * e0 * inv);
            v1[t] = __expf(-e1 * e1 * inv);
            v2[t] = __expf(-e2 * e2 * inv);
            v3[t] = __expf(-e3 * e3 * inv);
            s0 += v0[t]; s1 += v1[t]; s2 += v2[t]; s3 += v3[t];
        }
        den0 *= s0; den1 *= s1; den2 *= s2; den3 *= s3;
        p01_0 = pack2(v0[0], v0[1]); p23_0 = pack2(v0[2], v0[3]);
        p01_1 = pack2(v1[0], v1[1]); p23_1 = pack2(v1[2], v1[3]);
        p01_2 = pack2(v2[0], v2[1]); p23_2 = pack2(v2[2], v2[3]);
        p01_3 = pack2(v3[0], v3[1]); p23_3 = pack2(v3[2], v3[3]);
    }
    __syncthreads();

    const float4* C4 = (const float4*)sm;   // C4[j*1024 + quadIdx]

    ull acc[7][4];
#pragma unroll
    for (int j = 0; j < 7; j++)
#pragma unroll
        for (int e = 0; e < 4; e++) acc[j][e] = 0;

#pragma unroll 1
    for (int d1i = 0; d1i < 2; d1i++) {
        int d1 = d1h * 2 + d1i;
        ull A1_0 = mul2(A0_0, l1_0[d1]);
        ull A1_1 = mul2(A0_1, l1_1[d1]);
        ull A1_2 = mul2(A0_2, l1_2[d1]);
        ull A1_3 = mul2(A0_3, l1_3[d1]);
#pragma unroll 1
        for (int d2 = 0; d2 < 4; d2++) {
            ull A2_0 = mul2(A1_0, l2_0[d2]);
            ull A2_1 = mul2(A1_1, l2_1[d2]);
            ull A2_2 = mul2(A1_2, l2_2[d2]);
            ull A2_3 = mul2(A1_3, l2_3[d2]);
#pragma unroll 1
            for (int d3 = 0; d3 < 4; d3++) {
                ull A3_0 = mul2(A2_0, l3_0[d3]);
                ull A3_1 = mul2(A2_1, l3_1[d3]);
                ull A3_2 = mul2(A2_2, l3_2[d3]);
                ull A3_3 = mul2(A2_3, l3_3[d3]);
                int qb = ((d0 * 4 + d1) * 4 + d2) * 16 + d3 * 4;
#pragma unroll
                for (int d4 = 0; d4 < 4; d4++) {
                    ull A4_0 = mul2(A3_0, m4_0[d4]);
                    ull A4_1 = mul2(A3_1, m4_1[d4]);
                    ull A4_2 = mul2(A3_2, m4_2[d4]);
                    ull A4_3 = mul2(A3_3, m4_3[d4]);
                    ull w01_0 = mul2(A4_0, p01_0), w23_0 = mul2(A4_0, p23_0);
                    ull w01_1 = mul2(A4_1, p01_1), w23_1 = mul2(A4_1, p23_1);
                    ull w01_2 = mul2(A4_2, p01_2), w23_2 = mul2(A4_2, p23_2);
                    ull w01_3 = mul2(A4_3, p01_3), w23_3 = mul2(A4_3, p23_3);
                    int qq = qb + d4;
#pragma unroll
                    for (int j = 0; j < 7; j++) {
                        float4 c = C4[j * 1024 + qq];
                        ull cA = pack2(c.x, c.y);   // consecutive regs: no MOV
                        ull cB = pack2(c.z, c.w);
                        acc[j][0] = fma2(w01_0, cA, acc[j][0]);
                        acc[j][1] = fma2(w01_1, cA, acc[j][1]);
                        acc[j][2] = fma2(w01_2, cA, acc[j][2]);
                        acc[j][3] = fma2(w01_3, cA, acc[j][3]);
                        acc[j][0] = fma2(w23_0, cB, acc[j][0]);
                        acc[j][1] = fma2(w23_1, cB, acc[j][1]);
                        acc[j][2] = fma2(w23_2, cB, acc[j][2]);
                        acc[j][3] = fma2(w23_3, cB, acc[j][3]);
                    }
                }
            }
        }
    }

    // --- Collapse rule pairs: g[j][e] = lo + hi ---
    float g0[7], g1[7], g2[7], g3[7];
#pragma unroll
    for (int j = 0; j < 7; j++) {
        float lo, hi;
        unpack2(acc[j][0], lo, hi); g0[j] = lo + hi;
        unpack2(acc[j][1], lo, hi); g1[j] = lo + hi;
        unpack2(acc[j][2], lo, hi); g2[j] = lo + hi;
        unpack2(acc[j][3], lo, hi); g3[j] = lo + hi;
    }

    // --- Octant combine: REUSE table smem as staging (all reads done) ---
    __syncthreads();
    if (rs != 0) {
        float* base = sm + ((rs - 1) * 64 + eslot) * 29;
#pragma unroll
        for (int j = 0; j < 7; j++) {
            base[j * 4 + 0] = g0[j];
            base[j * 4 + 1] = g1[j];
            base[j * 4 + 2] = g2[j];
            base[j * 4 + 3] = g3[j];
        }
    }
    __syncthreads();

    if (rs == 0) {
#pragma unroll 1
        for (int o = 0; o < 7; o++) {
            const float* base = sm + (o * 64 + eslot) * 29;
#pragma unroll
            for (int j = 0; j < 7; j++) {
                g0[j] += base[j * 4 + 0];
                g1[j] += base[j * 4 + 1];
                g2[j] += base[j * 4 + 2];
                g3[j] += base[j * 4 + 3];
            }
        }
        float n0 = g0[6], n1 = g1[6], n2 = g2[6], n3 = g3[6];
#pragma unroll
        for (int i = 0; i < 6; i++) {
            n0 += g0[i] * x[b0 * 6 + i];
            n1 += g1[i] * x[b1 * 6 + i];
            n2 += g2[i] * x[b2 * 6 + i];
            n3 += g3[i] * x[b3 * 6 + i];
        }
        out[b0] = n0 / (den0 + 1e-8f);
        out[b1] = n1 / (den1 + 1e-8f);
        out[b2] = n2 / (den2 + 1e-8f);
        out[b3] = n3 / (den3 + 1e-8f);
    }
}

extern "C" void kernel_launch(void* const* d_in, const int* in_sizes, int n_in,
                              void* d_out, int out_size) {
    const float* x       = (const float*)d_in[0];
    const float* centers = (const float*)d_in[1];
    const float* sigmas  = (const float*)d_in[2];
    const float* cons    = (const float*)d_in[3];
    float* out = (float*)d_out;

    int B = in_sizes[0] / 6;        // 32768
    int blocks = B / 256;           // 128 (64 eslots x 4 batch quarters)

    cudaFuncSetAttribute(anfis_kernel,
                         cudaFuncAttributeMaxDynamicSharedMemorySize, SMEM_BYTES);

    anfis_kernel<<<blocks, THREADS, SMEM_BYTES>>>(x, centers, sigmas, cons, out);
}

// round 16
// speedup vs baseline: 1.0704x; 1.0387x over previous
#include <cuda_runtime.h>

typedef unsigned long long ull;

#define THREADS 512
#define SMEM_FLOATS 57344             // dup table: 3 quad arrays + 1 pair array
#define SMEM_BYTES  (SMEM_FLOATS * 4) // 229376 B (staging reuses table after mainloop)

__device__ __forceinline__ ull pack2(float lo, float hi) {
    ull r; asm("mov.b64 %0, {%1, %2};" : "=l"(r) : "f"(lo), "f"(hi)); return r;
}
__device__ __forceinline__ void unpack2(ull v, float& lo, float& hi) {
    asm("mov.b64 {%0, %1}, %2;" : "=f"(lo), "=f"(hi) : "l"(v));
}
__device__ __forceinline__ ull mul2(ull a, ull b) {
    ull d; asm("mul.rn.f32x2 %0, %1, %2;" : "=l"(d) : "l"(a), "l"(b)); return d;
}
__device__ __forceinline__ ull fma2(ull a, ull b, ull c) {
    ull d; asm("fma.rn.f32x2 %0, %1, %2, %3;" : "=l"(d) : "l"(a), "l"(b), "l"(c)); return d;
}

// ANFIS:
//   den[b] = prod_i (sum_t mu[b,i,t])
//   G[b,j] = sum_r w[b,r] * C[r,j]  (hierarchical base-4 partial products)
//   out[b] = (sum_j xa[b,j] * G[b,j]) / (den[b] + 1e-8)
// R7's proven register structure (element-pair f32x2, 4 elems/thread,
// membership pairs SHARED between the two packed elements) combined with
// the PRE-DUPLICATED coefficient table (zero duplication MOVs):
//   Q0[r]=(c0,c0,c1,c1), Q1[r]=(c2,c2,c3,c3), Q2[r]=(c4,c4,c5,c5),
//   P6[r]=(c6,c6)  -> 16 LDS / 4-rule body, batched 2 rules at a time
//   (28 transient regs, same as R7's 7x float4 batch).
// vs R9 (which spilled): the xv[24] arrays are NOT carried across the
// mainloop (x reloaded in the epilogue) -> ~24 regs of slack.
// 16 warps/block = 8 rule-octants (fixed d0, half of d1) x 2 quad-groups.
// Octant partials combined by REUSING the table smem after the mainloop.
__global__ void __launch_bounds__(THREADS, 1) anfis_kernel(
    const float* __restrict__ x,
    const float* __restrict__ centers,
    const float* __restrict__ sigmas,
    const float* __restrict__ cons,
    float* __restrict__ out)
{
    extern __shared__ float sm[];

    // --- Build duplicated table ---
    for (int idx = threadIdx.x; idx < 4096 * 7; idx += THREADS) {
        int r = idx / 7;
        int j = idx - r * 7;
        float v = cons[idx];
        float* dst;
        if (j < 6) dst = sm + ((j >> 1) << 14) + r * 4 + ((j & 1) << 1);
        else       dst = sm + 49152 + r * 2;
        dst[0] = v;
        dst[1] = v;
    }

    int lane = threadIdx.x & 31;
    int warp = threadIdx.x >> 5;
    int g    = warp & 1;            // quad group
    int rs   = warp >> 1;           // rule octant 0..7
    int d0   = rs >> 1;
    int d1h  = rs & 1;
    int quad = g * 32 + lane;       // 0..63
    int q    = blockIdx.x * 64 + quad;

    int b0 = q, b1 = q + 8192, b2 = q + 16384, b3 = q + 24576;

    // --- Memberships (R7 structure): pairs P=(b0,b1), Q=(b2,b3), all regs;
    //     x values NOT kept (reloaded in epilogue) ---
    ull A0P = 0, A0Q = 0;
    ull m1P[2], m1Q[2];
    ull mu2P[4], mu2Q[4], mu3P[4], mu3Q[4], mu4P[4], mu4Q[4], mu5P[4], mu5Q[4];
    float den0 = 1.0f, den1 = 1.0f, den2 = 1.0f, den3 = 1.0f;

#pragma unroll
    for (int i = 0; i < 6; i++) {
        float x0 = x[b0 * 6 + i];
        float x1 = x[b1 * 6 + i];
        float x2 = x[b2 * 6 + i];
        float x3 = x[b3 * 6 + i];
        float s0 = 0.0f, s1 = 0.0f, s2 = 0.0f, s3 = 0.0f;
#pragma unroll
        for (int t = 0; t < 4; t++) {
            float c   = centers[i * 4 + t];
            float sg  = fabsf(sigmas[i * 4 + t]) + 1e-6f;
            float inv = 0.5f / (sg * sg);
            float e0 = x0 - c, e1 = x1 - c, e2 = x2 - c, e3 = x3 - c;
            float v0 = __expf(-e0 * e0 * inv);
            float v1 = __expf(-e1 * e1 * inv);
            float v2 = __expf(-e2 * e2 * inv);
            float v3 = __expf(-e3 * e3 * inv);
            s0 += v0; s1 += v1; s2 += v2; s3 += v3;
            ull P = pack2(v0, v1);
            ull Q = pack2(v2, v3);
            if (i == 0) { if (t == d0) { A0P = P; A0Q = Q; } }
            else if (i == 1) {
                if (t == d1h * 2)     { m1P[0] = P; m1Q[0] = Q; }
                if (t == d1h * 2 + 1) { m1P[1] = P; m1Q[1] = Q; }
            }
            else if (i == 2) { mu2P[t] = P; mu2Q[t] = Q; }
            else if (i == 3) { mu3P[t] = P; mu3Q[t] = Q; }
            else if (i == 4) { mu4P[t] = P; mu4Q[t] = Q; }
            else             { mu5P[t] = P; mu5Q[t] = Q; }
        }
        den0 *= s0; den1 *= s1; den2 *= s2; den3 *= s3;
    }
    __syncthreads();

    const ulonglong2* Q0 = (const ulonglong2*)(sm);
    const ulonglong2* Q1 = (const ulonglong2*)(sm + 16384);
    const ulonglong2* Q2 = (const ulonglong2*)(sm + 32768);
    const ull*        P6 = (const ull*)(sm + 49152);

    ull accP[7], accQ[7];
#pragma unroll
    for (int j = 0; j < 7; j++) { accP[j] = 0; accQ[j] = 0; }

#pragma unroll 1
    for (int d1i = 0; d1i < 2; d1i++) {
        ull A1P = mul2(A0P, m1P[d1i]);
        ull A1Q = mul2(A0Q, m1Q[d1i]);
        int d1 = d1h * 2 + d1i;
#pragma unroll 1
        for (int d2 = 0; d2 < 4; d2++) {
            ull A2P = mul2(A1P, mu2P[d2]);
            ull A2Q = mul2(A1Q, mu2Q[d2]);
#pragma unroll
            for (int d3 = 0; d3 < 4; d3++) {
                ull A3P = mul2(A2P, mu3P[d3]);
                ull A3Q = mul2(A2Q, mu3Q[d3]);
#pragma unroll
                for (int d4 = 0; d4 < 4; d4++) {
                    ull A4P = mul2(A3P, mu4P[d4]);
                    ull A4Q = mul2(A3Q, mu4Q[d4]);
                    ull wP0 = mul2(A4P, mu5P[0]);
                    ull wP1 = mul2(A4P, mu5P[1]);
                    ull wP2 = mul2(A4P, mu5P[2]);
                    ull wP3 = mul2(A4P, mu5P[3]);
                    ull wQ0 = mul2(A4Q, mu5Q[0]);
                    ull wQ1 = mul2(A4Q, mu5Q[1]);
                    ull wQ2 = mul2(A4Q, mu5Q[2]);
                    ull wQ3 = mul2(A4Q, mu5Q[3]);
                    int rr = (((d0 * 4 + d1) * 4 + d2) * 16 + d3 * 4 + d4) * 4;

                    // rules rr, rr+1: batch 8 LDS (28 regs), then 28 fma2
                    {
                        ulonglong2 a0 = Q0[rr],     a1 = Q1[rr],     a2 = Q2[rr];
                        ull        a6 = P6[rr];
                        ulonglong2 c0 = Q0[rr + 1], c1 = Q1[rr + 1], c2 = Q2[rr + 1];
                        ull        c6 = P6[rr + 1];
                        accP[0] = fma2(wP0, a0.x, accP[0]);
                        accQ[0] = fma2(wQ0, a0.x, accQ[0]);
                        accP[1] = fma2(wP0, a0.y, accP[1]);
                        accQ[1] = fma2(wQ0, a0.y, accQ[1]);
                        accP[2] = fma2(wP0, a1.x, accP[2]);
                        accQ[2] = fma2(wQ0, a1.x, accQ[2]);
                        accP[3] = fma2(wP0, a1.y, accP[3]);
                        accQ[3] = fma2(wQ0, a1.y, accQ[3]);
                        accP[4] = fma2(wP0, a2.x, accP[4]);
                        accQ[4] = fma2(wQ0, a2.x, accQ[4]);
                        accP[5] = fma2(wP0, a2.y, accP[5]);
                        accQ[5] = fma2(wQ0, a2.y, accQ[5]);
                        accP[6] = fma2(wP0, a6,  accP[6]);
                        accQ[6] = fma2(wQ0, a6,  accQ[6]);
                        accP[0] = fma2(wP1, c0.x, accP[0]);
                        accQ[0] = fma2(wQ1, c0.x, accQ[0]);
                        accP[1] = fma2(wP1, c0.y, accP[1]);
                        accQ[1] = fma2(wQ1, c0.y, accQ[1]);
                        accP[2] = fma2(wP1, c1.x, accP[2]);
                        accQ[2] = fma2(wQ1, c1.x, accQ[2]);
                        accP[3] = fma2(wP1, c1.y, accP[3]);
                        accQ[3] = fma2(wQ1, c1.y, accQ[3]);
                        accP[4] = fma2(wP1, c2.x, accP[4]);
                        accQ[4] = fma2(wQ1, c2.x, accQ[4]);
                        accP[5] = fma2(wP1, c2.y, accP[5]);
                        accQ[5] = fma2(wQ1, c2.y, accQ[5]);
                        accP[6] = fma2(wP1, c6,  accP[6]);
                        accQ[6] = fma2(wQ1, c6,  accQ[6]);
                    }
                    // rules rr+2, rr+3
                    {
                        ulonglong2 a0 = Q0[rr + 2], a1 = Q1[rr + 2], a2 = Q2[rr + 2];
                        ull        a6 = P6[rr + 2];
                        ulonglong2 c0 = Q0[rr + 3], c1 = Q1[rr + 3], c2 = Q2[rr + 3];
                        ull        c6 = P6[rr + 3];
                        accP[0] = fma2(wP2, a0.x, accP[0]);
                        accQ[0] = fma2(wQ2, a0.x, accQ[0]);
                        accP[1] = fma2(wP2, a0.y, accP[1]);
                        accQ[1] = fma2(wQ2, a0.y, accQ[1]);
                        accP[2] = fma2(wP2, a1.x, accP[2]);
                        accQ[2] = fma2(wQ2, a1.x, accQ[2]);
                        accP[3] = fma2(wP2, a1.y, accP[3]);
                        accQ[3] = fma2(wQ2, a1.y, accQ[3]);
                        accP[4] = fma2(wP2, a2.x, accP[4]);
                        accQ[4] = fma2(wQ2, a2.x, accQ[4]);
                        accP[5] = fma2(wP2, a2.y, accP[5]);
                        accQ[5] = fma2(wQ2, a2.y, accQ[5]);
                        accP[6] = fma2(wP2, a6,  accP[6]);
                        accQ[6] = fma2(wQ2, a6,  accQ[6]);
                        accP[0] = fma2(wP3, c0.x, accP[0]);
                        accQ[0] = fma2(wQ3, c0.x, accQ[0]);
                        accP[1] = fma2(wP3, c0.y, accP[1]);
                        accQ[1] = fma2(wQ3, c0.y, accQ[1]);
                        accP[2] = fma2(wP3, c1.x, accP[2]);
                        accQ[2] = fma2(wQ3, c1.x, accQ[2]);
                        accP[3] = fma2(wP3, c1.y, accP[3]);
                        accQ[3] = fma2(wQ3, c1.y, accQ[3]);
                        accP[4] = fma2(wP3, c2.x, accP[4]);
                        accQ[4] = fma2(wQ3, c2.x, accQ[4]);
                        accP[5] = fma2(wP3, c2.y, accP[5]);
                        accQ[5] = fma2(wQ3, c2.y, accQ[5]);
                        accP[6] = fma2(wP3, c6,  accP[6]);
                        accQ[6] = fma2(wQ3, c6,  accQ[6]);
                    }
                }
            }
        }
    }

    // --- Octant combine: REUSE table smem as staging (all reads done) ---
    __syncthreads();
    if (rs != 0) {
        float* base = sm + ((rs - 1) * 64 + quad) * 29;
#pragma unroll
        for (int j = 0; j < 7; j++) {
            float a, bf, c2, d2v;
            unpack2(accP[j], a, bf);
            unpack2(accQ[j], c2, d2v);
            base[j * 4 + 0] = a;
            base[j * 4 + 1] = bf;
            base[j * 4 + 2] = c2;
            base[j * 4 + 3] = d2v;
        }
    }
    __syncthreads();

    if (rs == 0) {
        float g0[7], g1[7], g2[7], g3[7];
#pragma unroll
        for (int j = 0; j < 7; j++) {
            unpack2(accP[j], g0[j], g1[j]);
            unpack2(accQ[j], g2[j], g3[j]);
        }
#pragma unroll 1
        for (int o = 0; o < 7; o++) {
            const float* base = sm + (o * 64 + quad) * 29;
#pragma unroll
            for (int j = 0; j < 7; j++) {
                g0[j] += base[j * 4 + 0];
                g1[j] += base[j * 4 + 1];
                g2[j] += base[j * 4 + 2];
                g3[j] += base[j * 4 + 3];
            }
        }
        float n0 = g0[6], n1 = g1[6], n2 = g2[6], n3 = g3[6];
#pragma unroll
        for (int i = 0; i < 6; i++) {
            n0 += g0[i] * x[b0 * 6 + i];
            n1 += g1[i] * x[b1 * 6 + i];
            n2 += g2[i] * x[b2 * 6 + i];
            n3 += g3[i] * x[b3 * 6 + i];
        }
        out[b0] = n0 / (den0 + 1e-8f);
        out[b1] = n1 / (den1 + 1e-8f);
        out[b2] = n2 / (den2 + 1e-8f);
        out[b3] = n3 / (den3 + 1e-8f);
    }
}

extern "C" void kernel_launch(void* const* d_in, const int* in_sizes, int n_in,
                              void* d_out, int out_size) {
    const float* x       = (const float*)d_in[0];
    const float* centers = (const float*)d_in[1];
    const float* sigmas  = (const float*)d_in[2];
    const float* cons    = (const float*)d_in[3];
    float* out = (float*)d_out;

    int B = in_sizes[0] / 6;        // 32768
    int blocks = B / 256;           // 128 (64 quads x 4 batch quarters)

    cudaFuncSetAttribute(anfis_kernel,
                         cudaFuncAttributeMaxDynamicSharedMemorySize, SMEM_BYTES);

    anfis_kernel<<<blocks, THREADS, SMEM_BYTES>>>(x, centers, sigmas, cons, out);
}

// round 17
// speedup vs baseline: 1.1718x; 1.0947x over previous
#include <cuda_runtime.h>

typedef unsigned long long ull;

#define THREADS 512
#define TABLE_FLOATS (7 * 4096)              // j-major coefficient table
#define RED_FLOATS   (7 * 64 * 29)           // 7 octants x 64 quads x 29-float rows
#define SMEM_BYTES   ((TABLE_FLOATS + RED_FLOATS) * 4)   // 166656 B

__device__ __forceinline__ ull pack2(float lo, float hi) {
    ull r; asm("mov.b64 %0, {%1, %2};" : "=l"(r) : "f"(lo), "f"(hi)); return r;
}
__device__ __forceinline__ void unpack2(ull v, float& lo, float& hi) {
    asm("mov.b64 {%0, %1}, %2;" : "=f"(lo), "=f"(hi) : "l"(v));
}
__device__ __forceinline__ ull mul2(ull a, ull b) {
    ull d; asm("mul.rn.f32x2 %0, %1, %2;" : "=l"(d) : "l"(a), "l"(b)); return d;
}
__device__ __forceinline__ ull fma2(ull a, ull b, ull c) {
    ull d; asm("fma.rn.f32x2 %0, %1, %2, %3;" : "=l"(d) : "l"(a), "l"(b), "l"(c)); return d;
}

// ANFIS restructured:
//   den[b] = prod_i (sum_t mu[b,i,t])
//   G[b,j] = sum_r w[b,r] * C[r,j]
//   out[b] = (sum_j xa[b,j] * G[b,j]) / (den[b] + 1e-8)
// EXACTLY the R7 (58.1us) structure -- f32x2 packs ELEMENT PAIRS, 4 elements
// per thread (P=(b0,b1), Q=(b2,b3)), j-major float4 coefficient table,
// register-duplicated multipliers, 8 rule-octants x 2 quad-groups --
// with ONE change: the xv[4][6] arrays (24 registers) are no longer kept
// live across the mainloop; x is reloaded per-level during membership
// computation and again in the epilogue. This frees ~24 registers inside
// the only configuration that has ever run clean, letting ptxas cut the
// residual spills (R7: alu 5.5% at regs=128) and hoist the 7 float4 LDS.
__global__ void __launch_bounds__(THREADS, 1) anfis_kernel(
    const float* __restrict__ x,
    const float* __restrict__ centers,
    const float* __restrict__ sigmas,
    const float* __restrict__ cons,
    float* __restrict__ out)
{
    extern __shared__ float sm[];
    float* red = sm + TABLE_FLOATS;

    // --- Build j-major table: sm[j*4096 + r] = cons[r*7 + j] ---
    for (int idx = threadIdx.x; idx < TABLE_FLOATS; idx += THREADS) {
        int j = idx >> 12;
        int r = idx & 4095;
        sm[idx] = cons[r * 7 + j];
    }

    int lane = threadIdx.x & 31;
    int warp = threadIdx.x >> 5;
    int g    = warp & 1;            // which 32-quad group
    int rs   = warp >> 1;           // rule octant 0..7
    int d0   = rs >> 1;             // fixed level-0 digit
    int d1h  = rs & 1;              // which half of level-1 digits
    int quad = g * 32 + lane;       // 0..63 within block
    int q    = blockIdx.x * 64 + quad;

    int b0 = q, b1 = q + 8192, b2 = q + 16384, b3 = q + 24576;

    // --- Memberships for 4 elements; pairs P=(b0,b1), Q=(b2,b3).
    //     x loaded per-level (NOT kept across the mainloop). ---
    ull A0P = 0, A0Q = 0;                 // mu0[d0]
    ull m1P[2], m1Q[2];                   // mu1 at d1h*2 + {0,1}
    ull mu2P[4], mu2Q[4], mu3P[4], mu3Q[4];
    ull mu4P[4], mu4Q[4], mu5P[4], mu5Q[4];
    float den0 = 1.0f, den1 = 1.0f, den2 = 1.0f, den3 = 1.0f;

#pragma unroll
    for (int i = 0; i < 6; i++) {
        float x0 = x[b0 * 6 + i];
        float x1 = x[b1 * 6 + i];
        float x2 = x[b2 * 6 + i];
        float x3 = x[b3 * 6 + i];
        float s0 = 0.0f, s1 = 0.0f, s2 = 0.0f, s3 = 0.0f;
#pragma unroll
        for (int t = 0; t < 4; t++) {
            float c   = centers[i * 4 + t];
            float sg  = fabsf(sigmas[i * 4 + t]) + 1e-6f;
            float inv = 0.5f / (sg * sg);
            float e0 = x0 - c, e1 = x1 - c, e2 = x2 - c, e3 = x3 - c;
            float m0 = __expf(-e0 * e0 * inv);
            float m1 = __expf(-e1 * e1 * inv);
            float m2 = __expf(-e2 * e2 * inv);
            float m3 = __expf(-e3 * e3 * inv);
            s0 += m0; s1 += m1; s2 += m2; s3 += m3;
            ull P = pack2(m0, m1);
            ull Q = pack2(m2, m3);
            if (i == 0) { if (t == d0) { A0P = P; A0Q = Q; } }
            else if (i == 1) {
                if (t == d1h * 2)     { m1P[0] = P; m1Q[0] = Q; }
                if (t == d1h * 2 + 1) { m1P[1] = P; m1Q[1] = Q; }
            }
            else if (i == 2) { mu2P[t] = P; mu2Q[t] = Q; }
            else if (i == 3) { mu3P[t] = P; mu3Q[t] = Q; }
            else if (i == 4) { mu4P[t] = P; mu4Q[t] = Q; }
            else             { mu5P[t] = P; mu5Q[t] = Q; }
        }
        den0 *= s0; den1 *= s1; den2 *= s2; den3 *= s3;
    }
    __syncthreads();

    const float4* C4 = (const float4*)sm;   // C4[j*1024 + quadIdx]

    ull accP[7], accQ[7];
#pragma unroll
    for (int j = 0; j < 7; j++) { accP[j] = 0; accQ[j] = 0; }

#pragma unroll 1
    for (int d1i = 0; d1i < 2; d1i++) {
        ull A1P = mul2(A0P, m1P[d1i]);
        ull A1Q = mul2(A0Q, m1Q[d1i]);
        int d1 = d1h * 2 + d1i;
#pragma unroll 1
        for (int d2 = 0; d2 < 4; d2++) {
            ull A2P = mul2(A1P, mu2P[d2]);
            ull A2Q = mul2(A1Q, mu2Q[d2]);
#pragma unroll 1
            for (int d3 = 0; d3 < 4; d3++) {
                ull A3P = mul2(A2P, mu3P[d3]);
                ull A3Q = mul2(A2Q, mu3Q[d3]);
                int qb = d0 * 256 + d1 * 64 + d2 * 16 + d3 * 4;
#pragma unroll
                for (int d4 = 0; d4 < 4; d4++) {
                    ull A4P = mul2(A3P, mu4P[d4]);
                    ull A4Q = mul2(A3Q, mu4Q[d4]);
                    ull wP0 = mul2(A4P, mu5P[0]);
                    ull wP1 = mul2(A4P, mu5P[1]);
                    ull wP2 = mul2(A4P, mu5P[2]);
                    ull wP3 = mul2(A4P, mu5P[3]);
                    ull wQ0 = mul2(A4Q, mu5Q[0]);
                    ull wQ1 = mul2(A4Q, mu5Q[1]);
                    ull wQ2 = mul2(A4Q, mu5Q[2]);
                    ull wQ3 = mul2(A4Q, mu5Q[3]);
                    int qq = qb + d4;
#pragma unroll
                    for (int j = 0; j < 7; j++) {
                        float4 c = C4[j * 1024 + qq];
                        ull c0 = pack2(c.x, c.x);
                        ull c1 = pack2(c.y, c.y);
                        ull c2 = pack2(c.z, c.z);
                        ull c3 = pack2(c.w, c.w);
                        accP[j] = fma2(wP0, c0, accP[j]);
                        accQ[j] = fma2(wQ0, c0, accQ[j]);
                        accP[j] = fma2(wP1, c1, accP[j]);
                        accQ[j] = fma2(wQ1, c1, accQ[j]);
                        accP[j] = fma2(wP2, c2, accP[j]);
                        accQ[j] = fma2(wQ2, c2, accQ[j]);
                        accP[j] = fma2(wP3, c3, accP[j]);
                        accQ[j] = fma2(wQ3, c3, accQ[j]);
                    }
                }
            }
        }
    }

    // --- Combine 8 rule-octants per quad: octants 1..7 stage to smem ---
    if (rs != 0) {
        float* base = red + ((rs - 1) * 64 + quad) * 29;
#pragma unroll
        for (int j = 0; j < 7; j++) {
            float a, bf, c2, d2v;
            unpack2(accP[j], a, bf);
            unpack2(accQ[j], c2, d2v);
            base[j * 4 + 0] = a;
            base[j * 4 + 1] = bf;
            base[j * 4 + 2] = c2;
            base[j * 4 + 3] = d2v;
        }
    }
    __syncthreads();

    if (rs == 0) {
        float g0[7], g1[7], g2[7], g3[7];
#pragma unroll
        for (int j = 0; j < 7; j++) {
            unpack2(accP[j], g0[j], g1[j]);
            unpack2(accQ[j], g2[j], g3[j]);
        }
#pragma unroll 1
        for (int o = 0; o < 7; o++) {
            const float* base = red + (o * 64 + quad) * 29;
#pragma unroll
            for (int j = 0; j < 7; j++) {
                g0[j] += base[j * 4 + 0];
                g1[j] += base[j * 4 + 1];
                g2[j] += base[j * 4 + 2];
                g3[j] += base[j * 4 + 3];
            }
        }
        float n0 = g0[6], n1 = g1[6], n2 = g2[6], n3 = g3[6];
#pragma unroll
        for (int i = 0; i < 6; i++) {
            n0 += g0[i] * x[b0 * 6 + i];
            n1 += g1[i] * x[b1 * 6 + i];
            n2 += g2[i] * x[b2 * 6 + i];
            n3 += g3[i] * x[b3 * 6 + i];
        }
        out[b0] = n0 / (den0 + 1e-8f);
        out[b1] = n1 / (den1 + 1e-8f);
        out[b2] = n2 / (den2 + 1e-8f);
        out[b3] = n3 / (den3 + 1e-8f);
    }
}

extern "C" void kernel_launch(void* const* d_in, const int* in_sizes, int n_in,
                              void* d_out, int out_size) {
    const float* x       = (const float*)d_in[0];
    const float* centers = (const float*)d_in[1];
    const float* sigmas  = (const float*)d_in[2];
    const float* cons    = (const float*)d_in[3];
    float* out = (float*)d_out;

    int B = in_sizes[0] / 6;        // 32768
    int blocks = B / 256;           // 128 (64 quads = 256 elements per block)

    cudaFuncSetAttribute(anfis_kernel,
                         cudaFuncAttributeMaxDynamicSharedMemorySize, SMEM_BYTES);

    anfis_kernel<<<blocks, THREADS, SMEM_BYTES>>>(x, centers, sigmas, cons, out);
}